// round 15
// baseline (speedup 1.0000x reference)
#include <cuda_runtime.h>
#include <cuda_fp16.h>
#include <cstdint>

// ---------------------------------------------------------------------------
// SpinConvSq2dSparse: N=8, Lx=Ly=128, C=16, K=9 (-> 5 effective taps), F_IN=64
// Round 15: R13 structure (4x16 tile, f16 MMA, register epilogue) with
// inter-tile software pipelining: each CTA does 2 tiles (t, t+1024) with
// double-buffered smem; tile1's load chunks are interleaved between tile0's
// GEMM taps so load latency hides under MMA work.
// ---------------------------------------------------------------------------

#define TPH   72     // f16 per tile pixel row (144B; ldmatrix conflict-free)
#define NTP   108    // tile pixels: 6 rows x 18 cols
#define TROW  18     // tile pixels per x-row
#define NWFRAG 3840  // 2 arrays x 5 taps x 6 nt x 2 regs x 32 lanes (u32)
#define TILE_BYTES (NTP * TPH * 2)                // 15552
#define SMEM_BYTES (2 * TILE_BYTES)               // 31104 B

__device__ uint32_t g_Bfrag[NWFRAG];

// ---- mma helpers (sm_100a) ----
__device__ __forceinline__ void ldsm_x4(uint32_t* r, uint32_t addr) {
    asm volatile("ldmatrix.sync.aligned.m8n8.x4.shared.b16 {%0,%1,%2,%3}, [%4];"
                 : "=r"(r[0]), "=r"(r[1]), "=r"(r[2]), "=r"(r[3]) : "r"(addr));
}
__device__ __forceinline__ void mma_f16(float* c, const uint32_t* a, const uint32_t* b) {
    asm volatile("mma.sync.aligned.m16n8k16.row.col.f32.f16.f16.f32 "
                 "{%0,%1,%2,%3}, {%4,%5,%6,%7}, {%8,%9}, {%0,%1,%2,%3};"
                 : "+f"(c[0]), "+f"(c[1]), "+f"(c[2]), "+f"(c[3])
                 : "r"(a[0]), "r"(a[1]), "r"(a[2]), "r"(a[3]),
                   "r"(b[0]), "r"(b[1]));
}

// ---------------------------------------------------------------------------
// Effective weight (prefactors folded). tap0 = sum k=0..4 (center);
// tap1..4 = k=5..8 -> (x-1),(x+1),(y-1),(y+1).
// cols n: [0:16)=s110/a0-class, [16:32)=s101/b-class, [32:48)=t-class
// ---------------------------------------------------------------------------
__device__ __forceinline__ float effw(int isB, int tap, int c, int n,
                                      const float* w000, const float* w011,
                                      const float* w101, const float* w110,
                                      const float* w111) {
    const double C0  = 0.28209479177387814;
    const double C1  = 0.4886025119029199;
    const double IS3 = 0.57735026918962576;
    const double IS6 = 0.40824829046386302;
    const double PW0 = 0.058925565098878960;   // sqrt(1/(9*2*16))
    const double PW1 = 1.0 / 12.0;             // sqrt(3/(9*3*16))
    int cls = n >> 4, d = n & 15;
    int off = c * 16 + d;
    const float* w;
    double pf;
    if (!isB) {
        if (cls == 0)      { w = w110; pf = PW0 * IS3 * C1; }
        else if (cls == 1) { w = w101; pf = PW1 * C0 * IS3; }
        else               { w = w111; pf = PW1 * IS6 * C1; }
    } else {
        if (cls == 0)      { w = w000; pf = PW0 * C0; }
        else if (cls == 1) { w = w011; pf = PW1 * IS3 * C1; }
        else               return 0.f;
    }
    float s;
    if (tap == 0) {
        s = 0.f;
        #pragma unroll
        for (int k = 0; k < 5; k++) s += w[k * 256 + off];
    } else {
        s = w[(tap + 4) * 256 + off];
    }
    return (float)(pf * (double)s);
}

// Prep: emit B fragments in HMMA per-lane layout, packed f16x2.
__global__ void prep_weights(const float* __restrict__ w000,
                             const float* __restrict__ w011,
                             const float* __restrict__ w101,
                             const float* __restrict__ w110,
                             const float* __restrict__ w111) {
    int idx = blockIdx.x * blockDim.x + threadIdx.x;
    if (idx >= NWFRAG) return;
    int l   = idx & 31;
    int r   = (idx >> 5) & 1;
    int nt  = (idx >> 6) % 6;
    int tap = ((idx >> 6) / 6) % 5;
    int arr = idx / 1920;
    int n  = 8 * nt + (l >> 2);
    int c0 = 2 * (l & 3) + 8 * r;
    float v0 = effw(arr, tap, c0,     n, w000, w011, w101, w110, w111);
    float v1 = effw(arr, tap, c0 + 1, n, w000, w011, w101, w110, w111);
    __half2 h = __floats2half2_rn(v0, v1);
    g_Bfrag[idx] = *(uint32_t*)&h;
}

// ---------------------------------------------------------------------------
// Load one de-interleave item (idx in [0, 648)) of a 6x18 tile for (xb, yb).
// ---------------------------------------------------------------------------
__device__ __forceinline__ void load_item(__half* tileH, const float* featN,
                                          int xb, int yb, int idx) {
    int tp = idx / 6;
    int s  = idx - tp * 6;
    int tr = tp / TROW;
    int tc = tp - tr * TROW;
    int gx = (xb * 4 + tr + 127) & 127;
    int gy = (yb * 16 + tc + 127) & 127;
    const float* src = featN + ((size_t)gx * 128 + gy) * 64;
    __half* dst = tileH + tp * TPH;
    if (s < 2) {                           // x0 plane: 8 floats -> STS.128
        const float* u = src + 8 * s;
        float4 v0 = *(const float4*)(u);
        float4 v1 = *(const float4*)(u + 4);
        __half2 h0 = __floats2half2_rn(v0.x, v0.y);
        __half2 h1 = __floats2half2_rn(v0.z, v0.w);
        __half2 h2 = __floats2half2_rn(v1.x, v1.y);
        __half2 h3 = __floats2half2_rn(v1.z, v1.w);
        uint4 pk = make_uint4(*(uint32_t*)&h0, *(uint32_t*)&h1,
                              *(uint32_t*)&h2, *(uint32_t*)&h3);
        *(uint4*)(dst + 8 * s) = pk;
    } else {                               // x1 chunk: channels 4j..4j+3
        int j = s - 2;
        const float* u = src + 16 + 12 * j;
        float4 A = *(const float4*)(u);
        float4 B = *(const float4*)(u + 4);
        float4 C = *(const float4*)(u + 8);
        float f[12] = {A.x, A.y, A.z, A.w, B.x, B.y, B.z, B.w,
                       C.x, C.y, C.z, C.w};
        #pragma unroll
        for (int i = 0; i < 3; i++) {      // plane i
            __half2 lo = __floats2half2_rn(f[i],     f[3 + i]);
            __half2 hi = __floats2half2_rn(f[6 + i], f[9 + i]);
            uint2 pk;
            pk.x = *(uint32_t*)&lo;
            pk.y = *(uint32_t*)&hi;
            *(uint2*)(dst + (1 + i) * 16 + 4 * j) = pk;
        }
    }
}

// ---------------------------------------------------------------------------
// GEMM + epilogue for one tile. If PRELOAD, interleave the 3 load chunks of
// the next tile (into nextBuf, image featNextN) between taps 0..2.
// ---------------------------------------------------------------------------
template <bool PRELOAD>
__device__ __forceinline__ void gemm_epi(const __half* tileH, __half* nextBuf,
                                         const float* featNextN,
                                         int xb, int yb, int tid,
                                         const float* spinN, float* outN) {
    const int w    = tid >> 5;
    const int lane = tid & 31;
    const int pb   = w >> 1;                  // output row 0..3 (m-tile)
    const int par  = w & 1;                   // nt parity
    const int laneRow = lane & 15;
    const int cOffB   = (lane & 16) ? 16 : 0; // k-half byte offset
    const uint32_t tbase = (uint32_t)__cvta_generic_to_shared(tileH);
    const int rowc = (pb + 1) * TROW + 1 + laneRow;   // center tile pos

    float acc[4][3][4];
    #pragma unroll
    for (int g = 0; g < 4; g++)
        #pragma unroll
        for (int t = 0; t < 3; t++)
            #pragma unroll
            for (int i = 0; i < 4; i++) acc[g][t][i] = 0.f;

    const int tapoff[5] = {0, -TROW, TROW, -1, 1};   // center, x-1, x+1, y-1, y+1
    #pragma unroll
    for (int tap = 0; tap < 5; tap++) {
        if (PRELOAD && tap < 3) {            // interleave next-tile load chunk
            int idx = tid + 256 * tap;
            if (idx < NTP * 6) load_item(nextBuf, featNextN, xb, yb, idx);
        }
        const int rowb = (rowc + tapoff[tap]) * (TPH * 2) + cOffB;
        const uint32_t* bp = g_Bfrag + tap * 384 + lane;
        uint32_t B0[3][2], B1[2][2];
        #pragma unroll
        for (int t = 0; t < 3; t++) {
            const int nto = (par + 2 * t) * 64;
            B0[t][0] = __ldg(bp + nto);
            B0[t][1] = __ldg(bp + nto + 32);
        }
        #pragma unroll
        for (int t = 0; t < 2; t++) {
            const int nto = (par + 2 * t) * 64;
            B1[t][0] = __ldg(bp + 1920 + nto);
            B1[t][1] = __ldg(bp + 1920 + nto + 32);
        }
        #pragma unroll
        for (int g = 0; g < 4; g++) {
            const int fb2 = (g == 3) ? 0 : ((1 + g) << 5);   // plane byte offset
            uint32_t a[4];
            ldsm_x4(a, tbase + (uint32_t)(rowb + fb2));
            if (g < 3) {
                #pragma unroll
                for (int t = 0; t < 3; t++) mma_f16(acc[g][t], a, B0[t]);
            } else {
                #pragma unroll
                for (int t = 0; t < 2; t++) mma_f16(acc[3][t], a, B1[t]);
            }
        }
    }

    // register epilogue: lane owns cols c=(lane>>2)+8sel of row pb,
    // d values 8*par + 2*(lane&3) + {0,1}.
    const int m  = lane & 3;
    const int gx = xb * 4 + pb;
    #pragma unroll
    for (int sel = 0; sel < 2; sel++) {
        const int c = (lane >> 2) + 8 * sel;
        const int gy = yb * 16 + c;
        const size_t q = (size_t)gx * 128 + gy;
        const float* sp = spinN + q * 3;
        const float s0 = sp[1];
        const float s1 = sp[2];
        const float s2 = sp[0];

        float o0[2], o1[2][3];
        #pragma unroll
        for (int e = 0; e < 2; e++) {
            const int i = 2 * sel + e;
            const float a0 = acc[3][0][i];
            const float bv = acc[3][1][i];
            const float h0 = acc[0][0][i], h1 = acc[1][0][i], h2 = acc[2][0][i];
            const float a10 = acc[0][1][i], a11 = acc[1][1][i], a12 = acc[2][1][i];
            const float t0 = acc[0][2][i], t1 = acc[1][2][i], t2 = acc[2][2][i];
            o0[e] = a0 + h0 * s0 + h1 * s1 + h2 * s2;
            o1[e][0] = fmaf(bv, s0, a10) + (t1 * s2 - t2 * s1);
            o1[e][1] = fmaf(bv, s1, a11) + (t2 * s0 - t0 * s2);
            o1[e][2] = fmaf(bv, s2, a12) + (t0 * s1 - t1 * s0);
        }
        float* op = outN + q * 64;
        *(float2*)(op + 8 * par + 2 * m) = make_float2(o0[0], o0[1]);
        float* o1p = op + 16 + 24 * par + 6 * m;
        *(float2*)(o1p + 0) = make_float2(o1[0][0], o1[0][1]);
        *(float2*)(o1p + 2) = make_float2(o1[0][2], o1[1][0]);
        *(float2*)(o1p + 4) = make_float2(o1[1][1], o1[1][2]);
    }
}

// ---------------------------------------------------------------------------
// Main kernel: grid 1024. CTA b handles tiles b and b+1024 (n and n+4, same
// xb/yb), double-buffered and software-pipelined.
// ---------------------------------------------------------------------------
__global__ __launch_bounds__(256, 3)
void spinconv_kernel(const float* __restrict__ feat,
                     const float* __restrict__ spin,
                     float* __restrict__ out) {
    extern __shared__ float smem[];
    __half* buf0 = (__half*)smem;
    __half* buf1 = buf0 + NTP * TPH;

    const int b   = blockIdx.x;
    const int n0  = b >> 8;          // tile0 image (0..3); tile1 = n0+4
    const int xb  = (b >> 3) & 31;
    const int yb  = b & 7;
    const int tid = threadIdx.x;

    const float* featN0 = feat + (size_t)n0 * (128 * 128 * 64);
    const float* featN1 = featN0 + (size_t)4 * (128 * 128 * 64);
    const float* spinN0 = spin + (size_t)n0 * (128 * 128 * 3);
    const float* spinN1 = spinN0 + (size_t)4 * (128 * 128 * 3);
    float* outN0 = out + (size_t)n0 * (128 * 128 * 64);
    float* outN1 = outN0 + (size_t)4 * (128 * 128 * 64);

    // ---- full load of tile0 ----
    #pragma unroll
    for (int j = 0; j < 3; j++) {
        int idx = tid + 256 * j;
        if (idx < NTP * 6) load_item(buf0, featN0, xb, yb, idx);
    }
    __syncthreads();

    // ---- tile0 GEMM (+ interleaved tile1 load) + epilogue ----
    gemm_epi<true>(buf0, buf1, featN1, xb, yb, tid, spinN0, outN0);
    __syncthreads();

    // ---- tile1 GEMM + epilogue ----
    gemm_epi<false>(buf1, nullptr, nullptr, xb, yb, tid, spinN1, outN1);
}

// ---------------------------------------------------------------------------
extern "C" void kernel_launch(void* const* d_in, const int* in_sizes, int n_in,
                              void* d_out, int out_size) {
    const float* feat = (const float*)d_in[0];
    const float* spin = (const float*)d_in[1];
    const float* w000 = (const float*)d_in[2];
    const float* w011 = (const float*)d_in[3];
    const float* w101 = (const float*)d_in[4];
    const float* w110 = (const float*)d_in[5];
    const float* w111 = (const float*)d_in[6];
    float* out = (float*)d_out;

    (void)in_sizes; (void)n_in; (void)out_size;

    cudaFuncSetAttribute(spinconv_kernel,
                         cudaFuncAttributeMaxDynamicSharedMemorySize, SMEM_BYTES);

    prep_weights<<<(NWFRAG + 255) / 256, 256>>>(w000, w011, w101, w110, w111);
    spinconv_kernel<<<1024, 256, SMEM_BYTES>>>(feat, spin, out);
}

// round 16
// speedup vs baseline: 1.1875x; 1.1875x over previous
#include <cuda_runtime.h>
#include <cuda_fp16.h>
#include <cstdint>

// ---------------------------------------------------------------------------
// SpinConvSq2dSparse: N=8, Lx=Ly=128, C=16, K=9 (-> 5 effective taps), F_IN=64
// Round 16: R13 exactly (4x16 tile, f16 m16n8k16, register epilogue, direct
// global B-fragments) with ONE change: the tile-load phase is restructured as
// load-all-then-convert -- 3 fully unrolled predicated iterations whose 9
// LDG.128s are hoisted into a register block (MLP ~9 instead of ~3), then
// converted and stored. Cuts the exposed DRAM-latency chain ~3x.
// ---------------------------------------------------------------------------

#define TPH   72     // f16 per tile pixel row (144B; ldmatrix conflict-free)
#define NTP   108    // tile pixels: 6 rows x 18 cols
#define TROW  18     // tile pixels per x-row
#define NWFRAG 3840  // 2 arrays x 5 taps x 6 nt x 2 regs x 32 lanes (u32)
#define SMEM_BYTES (NTP * TPH * 2 + 192 * 4)   // tile 15552 + spin 768 = 16320 B

__device__ uint32_t g_Bfrag[NWFRAG];

// ---- mma helpers (sm_100a) ----
__device__ __forceinline__ void ldsm_x4(uint32_t* r, uint32_t addr) {
    asm volatile("ldmatrix.sync.aligned.m8n8.x4.shared.b16 {%0,%1,%2,%3}, [%4];"
                 : "=r"(r[0]), "=r"(r[1]), "=r"(r[2]), "=r"(r[3]) : "r"(addr));
}
__device__ __forceinline__ void mma_f16(float* c, const uint32_t* a, const uint32_t* b) {
    asm volatile("mma.sync.aligned.m16n8k16.row.col.f32.f16.f16.f32 "
                 "{%0,%1,%2,%3}, {%4,%5,%6,%7}, {%8,%9}, {%0,%1,%2,%3};"
                 : "+f"(c[0]), "+f"(c[1]), "+f"(c[2]), "+f"(c[3])
                 : "r"(a[0]), "r"(a[1]), "r"(a[2]), "r"(a[3]),
                   "r"(b[0]), "r"(b[1]));
}

// ---------------------------------------------------------------------------
// Effective weight (prefactors folded). tap0 = sum k=0..4 (center);
// tap1..4 = k=5..8 -> (x-1),(x+1),(y-1),(y+1).
// cols n: [0:16)=s110/a0-class, [16:32)=s101/b-class, [32:48)=t-class
// ---------------------------------------------------------------------------
__device__ __forceinline__ float effw(int isB, int tap, int c, int n,
                                      const float* w000, const float* w011,
                                      const float* w101, const float* w110,
                                      const float* w111) {
    const double C0  = 0.28209479177387814;
    const double C1  = 0.4886025119029199;
    const double IS3 = 0.57735026918962576;
    const double IS6 = 0.40824829046386302;
    const double PW0 = 0.058925565098878960;   // sqrt(1/(9*2*16))
    const double PW1 = 1.0 / 12.0;             // sqrt(3/(9*3*16))
    int cls = n >> 4, d = n & 15;
    int off = c * 16 + d;
    const float* w;
    double pf;
    if (!isB) {
        if (cls == 0)      { w = w110; pf = PW0 * IS3 * C1; }
        else if (cls == 1) { w = w101; pf = PW1 * C0 * IS3; }
        else               { w = w111; pf = PW1 * IS6 * C1; }
    } else {
        if (cls == 0)      { w = w000; pf = PW0 * C0; }
        else if (cls == 1) { w = w011; pf = PW1 * IS3 * C1; }
        else               return 0.f;
    }
    float s;
    if (tap == 0) {
        s = 0.f;
        #pragma unroll
        for (int k = 0; k < 5; k++) s += w[k * 256 + off];
    } else {
        s = w[(tap + 4) * 256 + off];
    }
    return (float)(pf * (double)s);
}

// Prep: emit B fragments in HMMA per-lane layout, packed f16x2.
// idx = arr*1920 + tap*384 + nt*64 + r*32 + lane
__global__ void prep_weights(const float* __restrict__ w000,
                             const float* __restrict__ w011,
                             const float* __restrict__ w101,
                             const float* __restrict__ w110,
                             const float* __restrict__ w111) {
    int idx = blockIdx.x * blockDim.x + threadIdx.x;
    if (idx >= NWFRAG) return;
    int l   = idx & 31;
    int r   = (idx >> 5) & 1;
    int nt  = (idx >> 6) % 6;
    int tap = ((idx >> 6) / 6) % 5;
    int arr = idx / 1920;
    int n  = 8 * nt + (l >> 2);
    int c0 = 2 * (l & 3) + 8 * r;
    float v0 = effw(arr, tap, c0,     n, w000, w011, w101, w110, w111);
    float v1 = effw(arr, tap, c0 + 1, n, w000, w011, w101, w110, w111);
    __half2 h = __floats2half2_rn(v0, v1);
    g_Bfrag[idx] = *(uint32_t*)&h;
}

// ---------------------------------------------------------------------------
// Main kernel: one CTA per (n, xb, yb): output tile 4 x-rows x 16 y-cols.
// 256 threads (8 warps). Warp w: m-tile (output row) pb=w>>1, nt parity w&1.
// ---------------------------------------------------------------------------
__global__ __launch_bounds__(256, 3)
void spinconv_kernel(const float* __restrict__ feat,
                     const float* __restrict__ spin,
                     float* __restrict__ out) {
    extern __shared__ float smem[];
    __half* tileH = (__half*)smem;              // f16 feat tile
    float*  sSpin = smem + (NTP * TPH) / 2;     // 192 floats (4 rows x 48)

    const int b   = blockIdx.x;
    const int n   = b >> 8;
    const int xb  = (b >> 3) & 31;   // 32 blocks of 4 x-rows
    const int yb  = b & 7;           // 8 blocks of 16 y-cols
    const int tid = threadIdx.x;

    // ---- spin LDG issued first (latency overlaps the feat loads) ----
    float4 spv;
    if (tid < 48) {
        int r = tid / 12, i = tid - r * 12;
        size_t q0 = ((size_t)n * 128 + xb * 4 + r) * 128 + yb * 16;
        spv = *(const float4*)(spin + q0 * 3 + i * 4);
    }

    // ---- tile load: batch ALL LDGs (MLP ~9), then convert + STS ----
    const size_t nbase = (size_t)n * (128 * 128 * 64);
    float4 R[3][3];
    int    sarr[3];
    __half* darr[3];
    #pragma unroll
    for (int it = 0; it < 3; it++) {
        int idx = tid + 256 * it;
        bool valid = idx < NTP * 6;
        sarr[it] = -1;
        if (valid) {
            int tp = idx / 6;
            int s  = idx - tp * 6;
            int tr = tp / TROW;
            int tc = tp - tr * TROW;
            int gx = (xb * 4 + tr + 127) & 127;
            int gy = (yb * 16 + tc + 127) & 127;
            const float* src = feat + nbase + ((size_t)gx * 128 + gy) * 64;
            sarr[it] = s;
            darr[it] = tileH + tp * TPH;
            if (s < 2) {
                const float* u = src + 8 * s;
                R[it][0] = *(const float4*)(u);
                R[it][1] = *(const float4*)(u + 4);
            } else {
                const float* u = src + 16 + 12 * (s - 2);
                R[it][0] = *(const float4*)(u);
                R[it][1] = *(const float4*)(u + 4);
                R[it][2] = *(const float4*)(u + 8);
            }
        }
    }
    if (tid < 48) {
        int r = tid / 12, i = tid - r * 12;
        *(float4*)(sSpin + r * 48 + i * 4) = spv;
    }
    #pragma unroll
    for (int it = 0; it < 3; it++) {
        int s = sarr[it];
        if (s < 0) continue;
        __half* dst = darr[it];
        if (s < 2) {                           // x0 plane: 8 floats -> STS.128
            float4 v0 = R[it][0];
            float4 v1 = R[it][1];
            __half2 h0 = __floats2half2_rn(v0.x, v0.y);
            __half2 h1 = __floats2half2_rn(v0.z, v0.w);
            __half2 h2 = __floats2half2_rn(v1.x, v1.y);
            __half2 h3 = __floats2half2_rn(v1.z, v1.w);
            uint4 pk = make_uint4(*(uint32_t*)&h0, *(uint32_t*)&h1,
                                  *(uint32_t*)&h2, *(uint32_t*)&h3);
            *(uint4*)(dst + 8 * s) = pk;
        } else {                               // x1 chunk: channels 4j..4j+3
            int j = s - 2;
            float4 A = R[it][0];
            float4 B = R[it][1];
            float4 C = R[it][2];
            float f[12] = {A.x, A.y, A.z, A.w, B.x, B.y, B.z, B.w,
                           C.x, C.y, C.z, C.w};
            #pragma unroll
            for (int i = 0; i < 3; i++) {      // plane i
                __half2 lo = __floats2half2_rn(f[i],     f[3 + i]);
                __half2 hi = __floats2half2_rn(f[6 + i], f[9 + i]);
                uint2 pk;
                pk.x = *(uint32_t*)&lo;
                pk.y = *(uint32_t*)&hi;
                *(uint2*)(dst + (1 + i) * 16 + 4 * j) = pk;
            }
        }
    }
    __syncthreads();

    // ---- tensor-core GEMM: acc[g][t][4], nt = par + 2t, all 4 g same rows.
    //      B fragments direct from global (L1-resident after first touch). ----
    const int w    = tid >> 5;
    const int lane = tid & 31;
    const int pb   = w >> 1;                  // output row 0..3 (m-tile)
    const int par  = w & 1;                   // nt parity
    const int laneRow = lane & 15;
    const int cOffB   = (lane & 16) ? 16 : 0; // k-half byte offset
    const uint32_t tbase = (uint32_t)__cvta_generic_to_shared(tileH);
    const int rowc = (pb + 1) * TROW + 1 + laneRow;   // center tile pos

    float acc[4][3][4];
    #pragma unroll
    for (int g = 0; g < 4; g++)
        #pragma unroll
        for (int t = 0; t < 3; t++)
            #pragma unroll
            for (int i = 0; i < 4; i++) acc[g][t][i] = 0.f;

    const int tapoff[5] = {0, -TROW, TROW, -1, 1};   // center, x-1, x+1, y-1, y+1
    #pragma unroll
    for (int tap = 0; tap < 5; tap++) {
        const int rowb = (rowc + tapoff[tap]) * (TPH * 2) + cOffB;
        // B fragments from global: WA all 3 nt, WB only nt par, par+2
        const uint32_t* bp = g_Bfrag + tap * 384 + lane;
        uint32_t B0[3][2], B1[2][2];
        #pragma unroll
        for (int t = 0; t < 3; t++) {
            const int nto = (par + 2 * t) * 64;
            B0[t][0] = __ldg(bp + nto);
            B0[t][1] = __ldg(bp + nto + 32);
        }
        #pragma unroll
        for (int t = 0; t < 2; t++) {
            const int nto = (par + 2 * t) * 64;
            B1[t][0] = __ldg(bp + 1920 + nto);
            B1[t][1] = __ldg(bp + 1920 + nto + 32);
        }
        #pragma unroll
        for (int g = 0; g < 4; g++) {
            const int fb2 = (g == 3) ? 0 : ((1 + g) << 5);   // plane byte offset
            uint32_t a[4];
            ldsm_x4(a, tbase + (uint32_t)(rowb + fb2));
            if (g < 3) {
                #pragma unroll
                for (int t = 0; t < 3; t++) mma_f16(acc[g][t], a, B0[t]);
            } else {
                #pragma unroll
                for (int t = 0; t < 2; t++) mma_f16(acc[3][t], a, B1[t]);
            }
        }
    }

    // ---- register epilogue: lane owns cols c=(lane>>2)+8sel of row pb,
    //      d values 8*par + 2*(lane&3) + {0,1}. ----
    const int m  = lane & 3;
    const int gx = xb * 4 + pb;
    #pragma unroll
    for (int sel = 0; sel < 2; sel++) {
        const int c = (lane >> 2) + 8 * sel;
        const int gy = yb * 16 + c;
        const size_t q = ((size_t)n * 128 + gx) * 128 + gy;
        const float* sp = sSpin + pb * 48 + c * 3;
        const float s0 = sp[1];
        const float s1 = sp[2];
        const float s2 = sp[0];

        float o0[2], o1[2][3];
        #pragma unroll
        for (int e = 0; e < 2; e++) {
            const int i = 2 * sel + e;
            const float a0 = acc[3][0][i];
            const float bv = acc[3][1][i];
            const float h0 = acc[0][0][i], h1 = acc[1][0][i], h2 = acc[2][0][i];
            const float a10 = acc[0][1][i], a11 = acc[1][1][i], a12 = acc[2][1][i];
            const float t0 = acc[0][2][i], t1 = acc[1][2][i], t2 = acc[2][2][i];
            o0[e] = a0 + h0 * s0 + h1 * s1 + h2 * s2;
            o1[e][0] = fmaf(bv, s0, a10) + (t1 * s2 - t2 * s1);
            o1[e][1] = fmaf(bv, s1, a11) + (t2 * s0 - t0 * s2);
            o1[e][2] = fmaf(bv, s2, a12) + (t0 * s1 - t1 * s0);
        }
        float* op = out + q * 64;
        *(float2*)(op + 8 * par + 2 * m) = make_float2(o0[0], o0[1]);
        float* o1p = op + 16 + 24 * par + 6 * m;
        *(float2*)(o1p + 0) = make_float2(o1[0][0], o1[0][1]);
        *(float2*)(o1p + 2) = make_float2(o1[0][2], o1[1][0]);
        *(float2*)(o1p + 4) = make_float2(o1[1][1], o1[1][2]);
    }
}

// ---------------------------------------------------------------------------
extern "C" void kernel_launch(void* const* d_in, const int* in_sizes, int n_in,
                              void* d_out, int out_size) {
    const float* feat = (const float*)d_in[0];
    const float* spin = (const float*)d_in[1];
    const float* w000 = (const float*)d_in[2];
    const float* w011 = (const float*)d_in[3];
    const float* w101 = (const float*)d_in[4];
    const float* w110 = (const float*)d_in[5];
    const float* w111 = (const float*)d_in[6];
    float* out = (float*)d_out;

    (void)in_sizes; (void)n_in; (void)out_size;

    cudaFuncSetAttribute(spinconv_kernel,
                         cudaFuncAttributeMaxDynamicSharedMemorySize, SMEM_BYTES);

    prep_weights<<<(NWFRAG + 255) / 256, 256>>>(w000, w011, w101, w110, w111);
    spinconv_kernel<<<8 * 32 * 8, 256, SMEM_BYTES>>>(feat, spin, out);
}

// round 17
// speedup vs baseline: 1.2295x; 1.0354x over previous
#include <cuda_runtime.h>
#include <cuda_fp16.h>
#include <cstdint>

// ---------------------------------------------------------------------------
// SpinConvSq2dSparse: N=8, Lx=Ly=128, C=16, K=9 (-> 5 effective taps), F_IN=64
// Round 17: R16 (4x16 tile, f16 m16n8k16, batched-MLP tile load, register
// epilogue) with scheduling fixes:
//   - ldsm/mma asm are NON-volatile -> ptxas may software-pipeline the
//     fully-unrolled 5-tap chain (hoist loads over MMAs)
//   - B fragments stored pair-adjacent -> one LDG.64 per fragment (was 2
//     dependent LDG.32), halving B-load issue slots
// ---------------------------------------------------------------------------

#define TPH   72     // f16 per tile pixel row (144B; ldmatrix conflict-free)
#define NTP   108    // tile pixels: 6 rows x 18 cols
#define TROW  18     // tile pixels per x-row
#define NWFRAG 3840  // 2 arrays x 5 taps x 6 nt x 32 lanes x 2 regs (u32)
#define SMEM_BYTES (NTP * TPH * 2 + 192 * 4)   // tile 15552 + spin 768 = 16320 B

__device__ uint32_t g_Bfrag[NWFRAG];

// ---- mma helpers (sm_100a); non-volatile: deps carry correctness ----
__device__ __forceinline__ void ldsm_x4(uint32_t* r, uint32_t addr) {
    asm("ldmatrix.sync.aligned.m8n8.x4.shared.b16 {%0,%1,%2,%3}, [%4];"
        : "=r"(r[0]), "=r"(r[1]), "=r"(r[2]), "=r"(r[3]) : "r"(addr));
}
__device__ __forceinline__ void mma_f16(float* c, const uint32_t* a, const uint32_t* b) {
    asm("mma.sync.aligned.m16n8k16.row.col.f32.f16.f16.f32 "
        "{%0,%1,%2,%3}, {%4,%5,%6,%7}, {%8,%9}, {%0,%1,%2,%3};"
        : "+f"(c[0]), "+f"(c[1]), "+f"(c[2]), "+f"(c[3])
        : "r"(a[0]), "r"(a[1]), "r"(a[2]), "r"(a[3]),
          "r"(b[0]), "r"(b[1]));
}

// ---------------------------------------------------------------------------
// Effective weight (prefactors folded). tap0 = sum k=0..4 (center);
// tap1..4 = k=5..8 -> (x-1),(x+1),(y-1),(y+1).
// cols n: [0:16)=s110/a0-class, [16:32)=s101/b-class, [32:48)=t-class
// ---------------------------------------------------------------------------
__device__ __forceinline__ float effw(int isB, int tap, int c, int n,
                                      const float* w000, const float* w011,
                                      const float* w101, const float* w110,
                                      const float* w111) {
    const double C0  = 0.28209479177387814;
    const double C1  = 0.4886025119029199;
    const double IS3 = 0.57735026918962576;
    const double IS6 = 0.40824829046386302;
    const double PW0 = 0.058925565098878960;   // sqrt(1/(9*2*16))
    const double PW1 = 1.0 / 12.0;             // sqrt(3/(9*3*16))
    int cls = n >> 4, d = n & 15;
    int off = c * 16 + d;
    const float* w;
    double pf;
    if (!isB) {
        if (cls == 0)      { w = w110; pf = PW0 * IS3 * C1; }
        else if (cls == 1) { w = w101; pf = PW1 * C0 * IS3; }
        else               { w = w111; pf = PW1 * IS6 * C1; }
    } else {
        if (cls == 0)      { w = w000; pf = PW0 * C0; }
        else if (cls == 1) { w = w011; pf = PW1 * IS3 * C1; }
        else               return 0.f;
    }
    float s;
    if (tap == 0) {
        s = 0.f;
        #pragma unroll
        for (int k = 0; k < 5; k++) s += w[k * 256 + off];
    } else {
        s = w[(tap + 4) * 256 + off];
    }
    return (float)(pf * (double)s);
}

// Prep: emit B fragments in HMMA per-lane layout, packed f16x2, with the two
// per-lane fragment regs ADJACENT: idx = arr*1920 + tap*384 + nt*64 + lane*2 + r
__global__ void prep_weights(const float* __restrict__ w000,
                             const float* __restrict__ w011,
                             const float* __restrict__ w101,
                             const float* __restrict__ w110,
                             const float* __restrict__ w111) {
    int idx = blockIdx.x * blockDim.x + threadIdx.x;
    if (idx >= NWFRAG) return;
    int r   = idx & 1;
    int l   = (idx >> 1) & 31;
    int nt  = (idx >> 6) % 6;
    int tap = ((idx >> 6) / 6) % 5;
    int arr = idx / 1920;
    int n  = 8 * nt + (l >> 2);
    int c0 = 2 * (l & 3) + 8 * r;
    float v0 = effw(arr, tap, c0,     n, w000, w011, w101, w110, w111);
    float v1 = effw(arr, tap, c0 + 1, n, w000, w011, w101, w110, w111);
    __half2 h = __floats2half2_rn(v0, v1);
    g_Bfrag[idx] = *(uint32_t*)&h;
}

// ---------------------------------------------------------------------------
// Main kernel: one CTA per (n, xb, yb): output tile 4 x-rows x 16 y-cols.
// 256 threads (8 warps). Warp w: m-tile (output row) pb=w>>1, nt parity w&1.
// ---------------------------------------------------------------------------
__global__ __launch_bounds__(256, 3)
void spinconv_kernel(const float* __restrict__ feat,
                     const float* __restrict__ spin,
                     float* __restrict__ out) {
    extern __shared__ float smem[];
    __half* tileH = (__half*)smem;              // f16 feat tile
    float*  sSpin = smem + (NTP * TPH) / 2;     // 192 floats (4 rows x 48)

    const int b   = blockIdx.x;
    const int n   = b >> 8;
    const int xb  = (b >> 3) & 31;   // 32 blocks of 4 x-rows
    const int yb  = b & 7;           // 8 blocks of 16 y-cols
    const int tid = threadIdx.x;

    // ---- spin LDG issued first (latency overlaps the feat loads) ----
    float4 spv;
    if (tid < 48) {
        int r = tid / 12, i = tid - r * 12;
        size_t q0 = ((size_t)n * 128 + xb * 4 + r) * 128 + yb * 16;
        spv = *(const float4*)(spin + q0 * 3 + i * 4);
    }

    // ---- tile load: batch ALL LDGs (MLP ~9), then convert + STS ----
    const size_t nbase = (size_t)n * (128 * 128 * 64);
    float4 R[3][3];
    int    sarr[3];
    __half* darr[3];
    #pragma unroll
    for (int it = 0; it < 3; it++) {
        int idx = tid + 256 * it;
        bool valid = idx < NTP * 6;
        sarr[it] = -1;
        if (valid) {
            int tp = idx / 6;
            int s  = idx - tp * 6;
            int tr = tp / TROW;
            int tc = tp - tr * TROW;
            int gx = (xb * 4 + tr + 127) & 127;
            int gy = (yb * 16 + tc + 127) & 127;
            const float* src = feat + nbase + ((size_t)gx * 128 + gy) * 64;
            sarr[it] = s;
            darr[it] = tileH + tp * TPH;
            if (s < 2) {
                const float* u = src + 8 * s;
                R[it][0] = *(const float4*)(u);
                R[it][1] = *(const float4*)(u + 4);
            } else {
                const float* u = src + 16 + 12 * (s - 2);
                R[it][0] = *(const float4*)(u);
                R[it][1] = *(const float4*)(u + 4);
                R[it][2] = *(const float4*)(u + 8);
            }
        }
    }
    if (tid < 48) {
        int r = tid / 12, i = tid - r * 12;
        *(float4*)(sSpin + r * 48 + i * 4) = spv;
    }
    #pragma unroll
    for (int it = 0; it < 3; it++) {
        int s = sarr[it];
        if (s < 0) continue;
        __half* dst = darr[it];
        if (s < 2) {                           // x0 plane: 8 floats -> STS.128
            float4 v0 = R[it][0];
            float4 v1 = R[it][1];
            __half2 h0 = __floats2half2_rn(v0.x, v0.y);
            __half2 h1 = __floats2half2_rn(v0.z, v0.w);
            __half2 h2 = __floats2half2_rn(v1.x, v1.y);
            __half2 h3 = __floats2half2_rn(v1.z, v1.w);
            uint4 pk = make_uint4(*(uint32_t*)&h0, *(uint32_t*)&h1,
                                  *(uint32_t*)&h2, *(uint32_t*)&h3);
            *(uint4*)(dst + 8 * s) = pk;
        } else {                               // x1 chunk: channels 4j..4j+3
            int j = s - 2;
            float4 A = R[it][0];
            float4 B = R[it][1];
            float4 C = R[it][2];
            float f[12] = {A.x, A.y, A.z, A.w, B.x, B.y, B.z, B.w,
                           C.x, C.y, C.z, C.w};
            #pragma unroll
            for (int i = 0; i < 3; i++) {      // plane i
                __half2 lo = __floats2half2_rn(f[i],     f[3 + i]);
                __half2 hi = __floats2half2_rn(f[6 + i], f[9 + i]);
                uint2 pk;
                pk.x = *(uint32_t*)&lo;
                pk.y = *(uint32_t*)&hi;
                *(uint2*)(dst + (1 + i) * 16 + 4 * j) = pk;
            }
        }
    }
    __syncthreads();

    // ---- tensor-core GEMM: acc[g][t][4], nt = par + 2t, all 4 g same rows.
    //      B fragments: one LDG.64 each, direct from global (L1-resident). ----
    const int w    = tid >> 5;
    const int lane = tid & 31;
    const int pb   = w >> 1;                  // output row 0..3 (m-tile)
    const int par  = w & 1;                   // nt parity
    const int laneRow = lane & 15;
    const int cOffB   = (lane & 16) ? 16 : 0; // k-half byte offset
    const uint32_t tbase = (uint32_t)__cvta_generic_to_shared(tileH);
    const int rowc = (pb + 1) * TROW + 1 + laneRow;   // center tile pos

    float acc[4][3][4];
    #pragma unroll
    for (int g = 0; g < 4; g++)
        #pragma unroll
        for (int t = 0; t < 3; t++)
            #pragma unroll
            for (int i = 0; i < 4; i++) acc[g][t][i] = 0.f;

    const int tapoff[5] = {0, -TROW, TROW, -1, 1};   // center, x-1, x+1, y-1, y+1
    #pragma unroll
    for (int tap = 0; tap < 5; tap++) {
        const int rowb = (rowc + tapoff[tap]) * (TPH * 2) + cOffB;
        // B fragments: WA all 3 nt, WB only nt par, par+2 (one LDG.64 each)
        const uint32_t* bp = g_Bfrag + tap * 384 + 2 * lane;
        uint32_t B0[3][2], B1[2][2];
        #pragma unroll
        for (int t = 0; t < 3; t++) {
            uint2 v = __ldg((const uint2*)(bp + (par + 2 * t) * 64));
            B0[t][0] = v.x; B0[t][1] = v.y;
        }
        #pragma unroll
        for (int t = 0; t < 2; t++) {
            uint2 v = __ldg((const uint2*)(bp + 1920 + (par + 2 * t) * 64));
            B1[t][0] = v.x; B1[t][1] = v.y;
        }
        #pragma unroll
        for (int g = 0; g < 4; g++) {
            const int fb2 = (g == 3) ? 0 : ((1 + g) << 5);   // plane byte offset
            uint32_t a[4];
            ldsm_x4(a, tbase + (uint32_t)(rowb + fb2));
            if (g < 3) {
                #pragma unroll
                for (int t = 0; t < 3; t++) mma_f16(acc[g][t], a, B0[t]);
            } else {
                #pragma unroll
                for (int t = 0; t < 2; t++) mma_f16(acc[3][t], a, B1[t]);
            }
        }
    }

    // ---- register epilogue: lane owns cols c=(lane>>2)+8sel of row pb,
    //      d values 8*par + 2*(lane&3) + {0,1}. ----
    const int m  = lane & 3;
    const int gx = xb * 4 + pb;
    #pragma unroll
    for (int sel = 0; sel < 2; sel++) {
        const int c = (lane >> 2) + 8 * sel;
        const int gy = yb * 16 + c;
        const size_t q = ((size_t)n * 128 + gx) * 128 + gy;
        const float* sp = sSpin + pb * 48 + c * 3;
        const float s0 = sp[1];
        const float s1 = sp[2];
        const float s2 = sp[0];

        float o0[2], o1[2][3];
        #pragma unroll
        for (int e = 0; e < 2; e++) {
            const int i = 2 * sel + e;
            const float a0 = acc[3][0][i];
            const float bv = acc[3][1][i];
            const float h0 = acc[0][0][i], h1 = acc[1][0][i], h2 = acc[2][0][i];
            const float a10 = acc[0][1][i], a11 = acc[1][1][i], a12 = acc[2][1][i];
            const float t0 = acc[0][2][i], t1 = acc[1][2][i], t2 = acc[2][2][i];
            o0[e] = a0 + h0 * s0 + h1 * s1 + h2 * s2;
            o1[e][0] = fmaf(bv, s0, a10) + (t1 * s2 - t2 * s1);
            o1[e][1] = fmaf(bv, s1, a11) + (t2 * s0 - t0 * s2);
            o1[e][2] = fmaf(bv, s2, a12) + (t0 * s1 - t1 * s0);
        }
        float* op = out + q * 64;
        *(float2*)(op + 8 * par + 2 * m) = make_float2(o0[0], o0[1]);
        float* o1p = op + 16 + 24 * par + 6 * m;
        *(float2*)(o1p + 0) = make_float2(o1[0][0], o1[0][1]);
        *(float2*)(o1p + 2) = make_float2(o1[0][2], o1[1][0]);
        *(float2*)(o1p + 4) = make_float2(o1[1][1], o1[1][2]);
    }
}

// ---------------------------------------------------------------------------
extern "C" void kernel_launch(void* const* d_in, const int* in_sizes, int n_in,
                              void* d_out, int out_size) {
    const float* feat = (const float*)d_in[0];
    const float* spin = (const float*)d_in[1];
    const float* w000 = (const float*)d_in[2];
    const float* w011 = (const float*)d_in[3];
    const float* w101 = (const float*)d_in[4];
    const float* w110 = (const float*)d_in[5];
    const float* w111 = (const float*)d_in[6];
    float* out = (float*)d_out;

    (void)in_sizes; (void)n_in; (void)out_size;

    cudaFuncSetAttribute(spinconv_kernel,
                         cudaFuncAttributeMaxDynamicSharedMemorySize, SMEM_BYTES);

    prep_weights<<<(NWFRAG + 255) / 256, 256>>>(w000, w011, w101, w110, w111);
    spinconv_kernel<<<8 * 32 * 8, 256, SMEM_BYTES>>>(feat, spin, out);
}